// round 1
// baseline (speedup 1.0000x reference)
#include <cuda_runtime.h>
#include <cuda_bf16.h>
#include <math.h>

// ---------------- problem constants ----------------
#define BATCH 4
#define NQ 4096
#define NL 1024
#define DV 512
#define DC 128
#define DI 512
#define DF 2048
#define NH 8
#define HD 64

// ---------------- device scratch ----------------
__device__ float g_sLv[BATCH * NL * DV];        //  8 MB
__device__ float g_sLc[BATCH * NL * DC];        //  2 MB
__device__ float g_vk [BATCH * NL * (2 * DI)];  // 16 MB  (v_v | k_v)
__device__ float g_kc [BATCH * NL * DI];        //  8 MB
__device__ float g_qv [BATCH * NQ * DI];        // 32 MB
__device__ float g_qc [BATCH * NQ * DI];        // 32 MB
__device__ float g_att[BATCH * NQ * DI];        // 32 MB
__device__ float g_y  [BATCH * NQ * DV];        // 32 MB
__device__ float g_h1 [BATCH * NQ * DF];        // 128 MB
__device__ float g_h2 [BATCH * NQ * DF];        // 128 MB

// ---------------- helpers ----------------
__device__ __forceinline__ float gelu_f(float x) {
    // jax.nn.gelu default (approximate=True, tanh form)
    float x3 = x * x * x;
    return 0.5f * x * (1.0f + tanhf(0.7978845608028654f * (x + 0.044715f * x3)));
}

// ---------------- LayerNorm (out-of-place ok, in-place ok) ----------------
__global__ void layernorm_kernel(const float* __restrict__ x,
                                 const float* __restrict__ g,
                                 const float* __restrict__ b,
                                 float* __restrict__ y,
                                 int D, float eps) {
    int row = blockIdx.x;
    const float* xr = x + (size_t)row * D;
    float s = 0.f, ss = 0.f;
    for (int i = threadIdx.x; i < D; i += blockDim.x) {
        float v = xr[i];
        s += v; ss += v * v;
    }
    __shared__ float rs[32], rss[32];
    #pragma unroll
    for (int off = 16; off; off >>= 1) {
        s  += __shfl_xor_sync(0xffffffffu, s,  off);
        ss += __shfl_xor_sync(0xffffffffu, ss, off);
    }
    int w = threadIdx.x >> 5, l = threadIdx.x & 31;
    if (l == 0) { rs[w] = s; rss[w] = ss; }
    __syncthreads();
    int nw = blockDim.x >> 5;
    if (threadIdx.x < 32) {
        s  = (l < nw) ? rs[l]  : 0.f;
        ss = (l < nw) ? rss[l] : 0.f;
        #pragma unroll
        for (int off = 16; off; off >>= 1) {
            s  += __shfl_xor_sync(0xffffffffu, s,  off);
            ss += __shfl_xor_sync(0xffffffffu, ss, off);
        }
        if (l == 0) { rs[0] = s; rss[0] = ss; }
    }
    __syncthreads();
    float mean = rs[0] / (float)D;
    float var  = rss[0] / (float)D - mean * mean;
    float inv  = rsqrtf(var + eps);
    float* yr = y + (size_t)row * D;
    for (int i = threadIdx.x; i < D; i += blockDim.x)
        yr[i] = (xr[i] - mean) * inv * g[i] + b[i];
}

// ---------------- RMSNorm in-place ----------------
__global__ void rmsnorm_kernel(float* __restrict__ x,
                               const float* __restrict__ g,
                               int D, float eps) {
    int row = blockIdx.x;
    float* xr = x + (size_t)row * D;
    float ss = 0.f;
    for (int i = threadIdx.x; i < D; i += blockDim.x) {
        float v = xr[i];
        ss += v * v;
    }
    __shared__ float rss[32];
    #pragma unroll
    for (int off = 16; off; off >>= 1)
        ss += __shfl_xor_sync(0xffffffffu, ss, off);
    int w = threadIdx.x >> 5, l = threadIdx.x & 31;
    if (l == 0) rss[w] = ss;
    __syncthreads();
    int nw = blockDim.x >> 5;
    if (threadIdx.x < 32) {
        ss = (l < nw) ? rss[l] : 0.f;
        #pragma unroll
        for (int off = 16; off; off >>= 1)
            ss += __shfl_xor_sync(0xffffffffu, ss, off);
        if (l == 0) rss[0] = ss;
    }
    __syncthreads();
    float inv = rsqrtf(rss[0] / (float)D + eps);
    for (int i = threadIdx.x; i < D; i += blockDim.x)
        xr[i] = xr[i] * inv * g[i];
}

// ---------------- generic tiled fp32 GEMM: C = A[M,K] @ W[K,N] + bias ----------------
// EPI: 0 = bias, 1 = bias + gelu
template <int EPI>
__global__ void gemm_kernel(const float* __restrict__ A,
                            const float* __restrict__ W,
                            const float* __restrict__ bias,
                            float* __restrict__ C,
                            int M, int K, int N) {
    __shared__ __align__(16) float As[16][68]; // [k][m] transposed
    __shared__ __align__(16) float Bs[16][68]; // [k][n]
    int tid = threadIdx.x;
    int tx = tid & 15, ty = tid >> 4;
    int bm = blockIdx.y * 64, bn = blockIdx.x * 64;
    float acc[4][4] = {};
    for (int k0 = 0; k0 < K; k0 += 16) {
        #pragma unroll
        for (int i = tid; i < 1024; i += 256) {
            int r = i >> 4, c = i & 15;
            As[c][r] = A[(size_t)(bm + r) * K + (k0 + c)];
        }
        #pragma unroll
        for (int i = tid; i < 1024; i += 256) {
            int r = i >> 6, c = i & 63;
            Bs[r][c] = W[(size_t)(k0 + r) * N + (bn + c)];
        }
        __syncthreads();
        #pragma unroll
        for (int kk = 0; kk < 16; kk++) {
            float4 a4 = *reinterpret_cast<const float4*>(&As[kk][ty * 4]);
            float4 b4 = *reinterpret_cast<const float4*>(&Bs[kk][tx * 4]);
            float a[4] = {a4.x, a4.y, a4.z, a4.w};
            float bb[4] = {b4.x, b4.y, b4.z, b4.w};
            #pragma unroll
            for (int i = 0; i < 4; i++)
                #pragma unroll
                for (int j = 0; j < 4; j++)
                    acc[i][j] += a[i] * bb[j];
        }
        __syncthreads();
    }
    #pragma unroll
    for (int i = 0; i < 4; i++) {
        int row = bm + ty * 4 + i;
        #pragma unroll
        for (int j = 0; j < 4; j++) {
            int col = bn + tx * 4 + j;
            float v = acc[i][j] + bias[col];
            if (EPI == 1) v = gelu_f(v);
            C[(size_t)row * N + col] = v;
        }
    }
}

// ---------------- fused dual-score flash attention ----------------
// score = q_c . k_c + lam * q_v . k_v == [q_c, lam*q_v] . [k_c, k_v]  (128-dim)
// grid: (NQ/64, H, B), 256 threads, online softmax, 64-wide kv tiles.
__global__ void attn_kernel(const float* __restrict__ qc,
                            const float* __restrict__ qv,
                            const float* __restrict__ kc,
                            const float* __restrict__ vkbuf, // [.,1024]: v_v | k_v
                            const float* __restrict__ lamp,
                            float* __restrict__ out) {
    int q0 = blockIdx.x * 64;
    int h  = blockIdx.y;
    int b  = blockIdx.z;
    extern __shared__ float smf[];
    float* Qs = smf;             // [64][129]
    float* Ks = Qs + 64 * 129;   // [64][129]
    float* Vs = Ks + 64 * 129;   // [64][65]
    float* Ps = Vs + 64 * 65;    // [64][65]

    int tid = threadIdx.x;
    int tx = tid & 15, ty = tid >> 4;
    float lam = lamp[0];

    for (int i = tid; i < 64 * 64; i += 256) {
        int r = i >> 6, d = i & 63;
        size_t base = ((size_t)(b * NQ + q0 + r)) * DI + h * HD + d;
        Qs[r * 129 + d]      = qc[base];
        Qs[r * 129 + 64 + d] = lam * qv[base];
    }

    float m_i[4], l_i[4], o[4][4];
    #pragma unroll
    for (int i = 0; i < 4; i++) {
        m_i[i] = -1e30f; l_i[i] = 0.f;
        #pragma unroll
        for (int j = 0; j < 4; j++) o[i][j] = 0.f;
    }

    for (int m0 = 0; m0 < NL; m0 += 64) {
        __syncthreads(); // protect Ks/Vs from prev PV; first iter: orders Q writes too
        for (int i = tid; i < 64 * 64; i += 256) {
            int r = i >> 6, d = i & 63;
            size_t kb = (size_t)(b * NL + m0 + r);
            Ks[r * 129 + d]      = kc[kb * DI + h * HD + d];
            Ks[r * 129 + 64 + d] = vkbuf[kb * (2 * DI) + DI + h * HD + d]; // k_v
            Vs[r * 65 + d]       = vkbuf[kb * (2 * DI) + h * HD + d];      // v_v
        }
        __syncthreads();

        float s[4][4];
        #pragma unroll
        for (int i = 0; i < 4; i++)
            #pragma unroll
            for (int j = 0; j < 4; j++) s[i][j] = 0.f;

        for (int kk = 0; kk < 128; kk++) {
            float a[4], bb[4];
            #pragma unroll
            for (int i = 0; i < 4; i++) a[i] = Qs[(ty * 4 + i) * 129 + kk];
            #pragma unroll
            for (int j = 0; j < 4; j++) bb[j] = Ks[(tx * 4 + j) * 129 + kk];
            #pragma unroll
            for (int i = 0; i < 4; i++)
                #pragma unroll
                for (int j = 0; j < 4; j++) s[i][j] += a[i] * bb[j];
        }

        // online softmax update (rows owned by 16 lanes of a half-warp)
        #pragma unroll
        for (int i = 0; i < 4; i++) {
            float mx = -1e30f;
            #pragma unroll
            for (int j = 0; j < 4; j++) {
                s[i][j] *= 0.125f; // 1/sqrt(64)
                mx = fmaxf(mx, s[i][j]);
            }
            #pragma unroll
            for (int off = 8; off; off >>= 1)
                mx = fmaxf(mx, __shfl_xor_sync(0xffffffffu, mx, off, 16));
            float mn = fmaxf(m_i[i], mx);
            float corr = __expf(m_i[i] - mn);
            float rsum = 0.f;
            #pragma unroll
            for (int j = 0; j < 4; j++) {
                float p = __expf(s[i][j] - mn);
                s[i][j] = p; rsum += p;
            }
            #pragma unroll
            for (int off = 8; off; off >>= 1)
                rsum += __shfl_xor_sync(0xffffffffu, rsum, off, 16);
            l_i[i] = l_i[i] * corr + rsum;
            m_i[i] = mn;
            #pragma unroll
            for (int j = 0; j < 4; j++) {
                o[i][j] *= corr;
                Ps[(ty * 4 + i) * 65 + tx * 4 + j] = s[i][j];
            }
        }
        __syncthreads();

        // O += P @ V
        for (int c = 0; c < 64; c++) {
            float a[4], bb[4];
            #pragma unroll
            for (int i = 0; i < 4; i++) a[i] = Ps[(ty * 4 + i) * 65 + c];
            #pragma unroll
            for (int j = 0; j < 4; j++) bb[j] = Vs[c * 65 + tx * 4 + j];
            #pragma unroll
            for (int i = 0; i < 4; i++)
                #pragma unroll
                for (int j = 0; j < 4; j++) o[i][j] += a[i] * bb[j];
        }
    }

    #pragma unroll
    for (int i = 0; i < 4; i++) {
        float invl = 1.f / l_i[i];
        int row = b * NQ + q0 + ty * 4 + i;
        #pragma unroll
        for (int j = 0; j < 4; j++)
            out[(size_t)row * DI + h * HD + tx * 4 + j] = o[i][j] * invl;
    }
}

// ---------------- host launcher ----------------
extern "C" void kernel_launch(void* const* d_in, const int* in_sizes, int n_in,
                              void* d_out, int out_size) {
    const float* coords = (const float*)d_in[0];
    const float* values = (const float*)d_in[1];
    const float* Lv     = (const float*)d_in[2];
    const float* Lc     = (const float*)d_in[3];
    const float* lam    = (const float*)d_in[4];
    const float* lvn_g  = (const float*)d_in[5];
    const float* lvn_b  = (const float*)d_in[6];
    const float* lcn_g  = (const float*)d_in[7];
    const float* lcn_b  = (const float*)d_in[8];
    const float* ck_w   = (const float*)d_in[9];
    const float* ck_b   = (const float*)d_in[10];
    const float* ck_g   = (const float*)d_in[11];
    const float* cq_w   = (const float*)d_in[12];
    const float* cq_b   = (const float*)d_in[13];
    const float* cq_g   = (const float*)d_in[14];
    const float* vq_w   = (const float*)d_in[15];
    const float* vq_b   = (const float*)d_in[16];
    const float* vq_g   = (const float*)d_in[17];
    const float* vk_w   = (const float*)d_in[18];
    const float* vk_b   = (const float*)d_in[19];
    const float* op_w   = (const float*)d_in[20];
    const float* op_b   = (const float*)d_in[21];
    const float* oln_g  = (const float*)d_in[22];
    const float* oln_b  = (const float*)d_in[23];
    const float* m1_w   = (const float*)d_in[24];
    const float* m1_b   = (const float*)d_in[25];
    const float* m2_w   = (const float*)d_in[26];
    const float* m2_b   = (const float*)d_in[27];
    const float* m3_w   = (const float*)d_in[28];
    const float* m3_b   = (const float*)d_in[29];
    float* out = (float*)d_out;

    float *sLv, *sLc, *vkb, *kcb, *qvb, *qcb, *attb, *yb, *h1, *h2;
    cudaGetSymbolAddress((void**)&sLv,  g_sLv);
    cudaGetSymbolAddress((void**)&sLc,  g_sLc);
    cudaGetSymbolAddress((void**)&vkb,  g_vk);
    cudaGetSymbolAddress((void**)&kcb,  g_kc);
    cudaGetSymbolAddress((void**)&qvb,  g_qv);
    cudaGetSymbolAddress((void**)&qcb,  g_qc);
    cudaGetSymbolAddress((void**)&attb, g_att);
    cudaGetSymbolAddress((void**)&yb,   g_y);
    cudaGetSymbolAddress((void**)&h1,   g_h1);
    cudaGetSymbolAddress((void**)&h2,   g_h2);

    const int BNL = BATCH * NL;   // 4096
    const int BNQ = BATCH * NQ;   // 16384

    // latent layernorms
    layernorm_kernel<<<BNL, 256>>>(Lv, lvn_g, lvn_b, sLv, DV, 1e-5f);
    layernorm_kernel<<<BNL, 128>>>(Lc, lcn_g, lcn_b, sLc, DC, 1e-5f);

    // projections
    gemm_kernel<0><<<dim3((2 * DI) / 64, BNL / 64), 256>>>(sLv, vk_w, vk_b, vkb, BNL, DV, 2 * DI);
    gemm_kernel<0><<<dim3(DI / 64, BNL / 64), 256>>>(sLc, ck_w, ck_b, kcb, BNL, DC, DI);
    rmsnorm_kernel<<<BNL, 256>>>(kcb, ck_g, DI, 1e-6f);
    gemm_kernel<0><<<dim3(DI / 64, BNQ / 64), 256>>>(values, vq_w, vq_b, qvb, BNQ, DV, DI);
    rmsnorm_kernel<<<BNQ, 256>>>(qvb, vq_g, DI, 1e-6f);
    gemm_kernel<0><<<dim3(DI / 64, BNQ / 64), 256>>>(coords, cq_w, cq_b, qcb, BNQ, DC, DI);
    rmsnorm_kernel<<<BNQ, 256>>>(qcb, cq_g, DI, 1e-6f);

    // dual-score flash attention
    size_t ash = (size_t)(64 * 129 * 2 + 64 * 65 * 2) * sizeof(float); // 99328 B
    cudaFuncSetAttribute(attn_kernel, cudaFuncAttributeMaxDynamicSharedMemorySize, (int)ash);
    attn_kernel<<<dim3(NQ / 64, NH, BATCH), 256, ash>>>(qcb, qvb, kcb, vkb, lam, attb);

    // output projection + LN + MLP
    gemm_kernel<0><<<dim3(DV / 64, BNQ / 64), 256>>>(attb, op_w, op_b, yb, BNQ, DI, DV);
    layernorm_kernel<<<BNQ, 256>>>(yb, oln_g, oln_b, yb, DV, 1e-5f);
    gemm_kernel<1><<<dim3(DF / 64, BNQ / 64), 256>>>(yb, m1_w, m1_b, h1, BNQ, DV, DF);
    gemm_kernel<1><<<dim3(DF / 64, BNQ / 64), 256>>>(h1, m2_w, m2_b, h2, BNQ, DF, DF);
    gemm_kernel<0><<<dim3(DV / 64, BNQ / 64), 256>>>(h2, m3_w, m3_b, out, BNQ, DF, DV);
}